// round 8
// baseline (speedup 1.0000x reference)
#include <cuda_runtime.h>
#include <cuda_bf16.h>
#include <cstdint>

// Problem constants: B=8, NWIN=256, N=64 tok, C=192, H=6, d=32
#define KT 16
typedef unsigned long long ull;

// ---------------- device scratch (no runtime allocation) ----------------
__device__ float g_wT [192*576];            // qkv_w transposed: [k][o]
__device__ float g_pwT[192*192];            // proj_w transposed: [k][o]
__device__ float g_v  [8*192*256*64];       // V: [b][c][win][tok]; overwritten in-place with attn out Y
__device__ float g_qg [8*192*256];          // [b][c][win]
__device__ float g_kg [8*192*256];

// ---------------- f32x2 helpers ----------------
__device__ __forceinline__ ull fma2(ull a, ull b, ull c){
    ull d; asm("fma.rn.f32x2 %0, %1, %2, %3;" : "=l"(d) : "l"(a), "l"(b), "l"(c)); return d;
}
__device__ __forceinline__ ull pack2(float lo, float hi){
    ull d; asm("mov.b64 %0, {%1, %2};" : "=l"(d) : "f"(lo), "f"(hi)); return d;
}
__device__ __forceinline__ float2 unpack2(ull v){
    float2 r; asm("mov.b64 {%0, %1}, %2;" : "=f"(r.x), "=f"(r.y) : "l"(v)); return r;
}

// Microtile step: 4 toks (tx, tx+16, tx+32, tx+48) x 12 outs, one k.
// xs layout [tok][193] (k-major access xs[tok*193+k]); ws row = 12 contiguous outs.
__device__ __forceinline__ void mma_step(const float* __restrict__ xs, int k, int tx,
                                         const float* __restrict__ wrow, ull acc[4][6]){
    ull xd[4];
    #pragma unroll
    for (int t = 0; t < 4; t++){
        float xv = xs[(tx + t*16)*193 + k];
        xd[t] = pack2(xv, xv);
    }
    ulonglong2 wA = *(const ulonglong2*)(wrow);
    ulonglong2 wB = *(const ulonglong2*)(wrow + 4);
    ulonglong2 wC = *(const ulonglong2*)(wrow + 8);
    ull wp[6] = {wA.x, wA.y, wB.x, wB.y, wC.x, wC.y};
    #pragma unroll
    for (int t = 0; t < 4; t++)
        #pragma unroll
        for (int p = 0; p < 6; p++)
            acc[t][p] = fma2(xd[t], wp[p], acc[t][p]);
}

// ---------------- kernel T: weight transpose to k-major ----------------
__global__ void kTrans(const float* __restrict__ qkv_w, const float* __restrict__ proj_w){
    int idx = blockIdx.x * 256 + threadIdx.x;
    if (idx < 576*192){ int o = idx / 192, k = idx % 192; g_wT [k*576 + o] = qkv_w [idx]; }
    if (idx < 192*192){ int o = idx / 192, k = idx % 192; g_pwT[k*192 + o] = proj_w[idx]; }
}

// ---------------- kernel A: QKV GEMM + grad magnitudes + V scatter ----------------
// smem: xs[64][193], ws[KT][192], qs[64][193]
#define SMEM_A ((64*193 + KT*192 + 64*193) * 4)

__global__ void __launch_bounds__(256, 2) kQKV(const float* __restrict__ x,
                                               const float* __restrict__ qkv_b){
    extern __shared__ float sm[];
    float* xs = sm;                  // [64][193]
    float* ws = sm + 64*193;         // [KT][192]
    float* qs = ws + KT*192;         // [64][193]
    const int tid = threadIdx.x;
    const int blk = blockIdx.x;      // b*256 + win
    const int b   = blk >> 8;
    const int win = blk & 255;
    const float* xw = x + (size_t)blk * (64*192);

    // load x window [tok][192] -> xs[tok][193]
    // float4 LDG (aligned: gmem row pitch 192) + 4 scalar STS (smem pitch 193 is
    // NOT 16B-aligned per row -> wide STS would trap; scalars are conflict-light)
    #pragma unroll
    for (int it = 0; it < 12; it++){
        int idx = it*256 + tid;           // 0..3071 = 64 tok * 48 quads
        int tok = idx / 48, c4 = idx % 48;
        float4 v = *(const float4*)(xw + tok*192 + c4*4);
        float* dst = xs + tok*193 + c4*4;
        dst[0] = v.x; dst[1] = v.y; dst[2] = v.z; dst[3] = v.w;
    }

    const int tx = tid & 15, ty = tid >> 4;
    const int obase = ty * 12;

    for (int s = 0; s < 3; s++){          // q, k, v chunks (192 outs each)
        ull acc[4][6];
        {
            const float* bp = qkv_b + s*192 + obase;
            #pragma unroll
            for (int p = 0; p < 6; p++){
                ull bb = pack2(bp[2*p], bp[2*p+1]);
                acc[0][p]=bb; acc[1][p]=bb; acc[2][p]=bb; acc[3][p]=bb;
            }
        }
        for (int kt = 0; kt < 192/KT; kt++){
            __syncthreads();              // xs ready / prev ws & qs consumers done
            #pragma unroll
            for (int it = 0; it < 3; it++){   // stage ws tile [KT][192]
                int idx = it*256 + tid;       // 0..767 quads
                int kk = idx / 48, o4 = idx % 48;
                *(float4*)(ws + kk*192 + o4*4) =
                    *(const float4*)(g_wT + (kt*KT+kk)*576 + s*192 + o4*4);
            }
            __syncthreads();
            #pragma unroll
            for (int kk = 0; kk < KT; kk++)
                mma_step(xs, kt*KT+kk, tx, ws + kk*192 + obase, acc);
        }
        __syncthreads();
        // write chunk to qs[tok][193] (scalar stores; rows not 16B-aligned)
        #pragma unroll
        for (int t = 0; t < 4; t++){
            float* q = qs + (tx + t*16)*193 + obase;
            #pragma unroll
            for (int p = 0; p < 6; p++){
                float2 v = unpack2(acc[t][p]);
                q[2*p] = v.x; q[2*p+1] = v.y;
            }
        }
        __syncthreads();
        if (s < 2){
            // grad magnitude per channel: 8x8 spatial, zero-padded forward diff
            if (tid < 192){
                float up[8];
                float sum = 0.f;
                #pragma unroll
                for (int yy = 0; yy < 8; yy++){
                    float left = 0.f;
                    #pragma unroll
                    for (int xx = 0; xx < 8; xx++){
                        float cur = qs[(yy*8 + xx)*193 + tid];
                        sum += fabsf(cur - left) + fabsf(cur - (yy ? up[xx] : 0.f));
                        left = cur; up[xx] = cur;
                    }
                }
                if (s == 0) g_qg[(b*192 + tid)*256 + win] = sum * 0.17677669529663687f; // *d^-0.5
                else        g_kg[(b*192 + tid)*256 + win] = sum;
            }
        } else {
            // scatter v -> g_v[b][c][win][tok]
            #pragma unroll
            for (int it = 0; it < 12; it++){
                int idx = it*256 + tid;       // 0..3071 = 192 ch * 16 tok-quads
                int o = idx / 16, t4 = idx % 16;
                float4 v;
                v.x = qs[(t4*4+0)*193 + o];
                v.y = qs[(t4*4+1)*193 + o];
                v.z = qs[(t4*4+2)*193 + o];
                v.w = qs[(t4*4+3)*193 + o];
                *(float4*)(g_v + ((size_t)(b*192 + o)*256 + win)*64 + t4*4) = v;
            }
        }
    }
}

// ---------------- kernel B: softmax(rank-1 scores) @ V per (b, channel) ----------
// smem: vsm[256][64], e32[32][260], qgs[256], red[256], rden[32]
#define E32P 260
#define SMEM_B ((16384 + 32*E32P + 256 + 256 + 32) * 4)

__global__ void __launch_bounds__(256, 2) kAttn(){
    extern __shared__ float sm[];
    float* vsm  = sm;                 // [256 win][64 tok]
    float* e32  = sm + 16384;         // [32 i][260]
    float* qgs  = e32 + 32*E32P;      // [256]
    float* red  = qgs + 256;          // [256]
    float* rden = red + 256;          // [32]
    const int tid = threadIdx.x;
    const int bc  = blockIdx.x;       // b*192 + c
    const size_t base = (size_t)bc * 256;
    float* vg = g_v + base * 64;

    #pragma unroll
    for (int it = 0; it < 16; it++){
        int idx = it*256 + tid;
        *(float4*)(vsm + idx*4) = *(const float4*)(vg + idx*4);
    }
    qgs[tid] = g_qg[base + tid];
    float kg = g_kg[base + tid];
    red[tid] = kg;
    __syncthreads();
    #pragma unroll
    for (int off = 128; off >= 1; off >>= 1){
        if (tid < off) red[tid] = fmaxf(red[tid], red[tid + off]);
        __syncthreads();
    }
    const float kv = kg - red[0];     // kg_j - kg_max  (<= 0), j = tid

    const int il  = tid >> 3;         // i slot within 32-row block (0..31)
    const int oct = tid & 7;          // token octet (0..7)
    const int rot = (oct*4 + il) & 31;

    for (int ib = 0; ib < 8; ib++){
        const float* qrow = qgs + ib*32;
        __syncthreads();              // previous e32 consumers done
        #pragma unroll
        for (int r = 0; r < 32; r++)
            e32[r*E32P + tid] = __expf(qrow[r] * kv);
        __syncthreads();
        {   // denominators: 8 rotated 32-j segments per i
            const float* er = e32 + il*E32P + oct*32;
            float ssum = 0.f;
            #pragma unroll
            for (int jj = 0; jj < 32; jj++)
                ssum += er[(jj + rot) & 31];
            red[tid] = ssum;
        }
        __syncthreads();
        if (tid < 32){
            float ssum = 0.f;
            #pragma unroll
            for (int g2 = 0; g2 < 8; g2++) ssum += red[tid*8 + g2];
            rden[tid] = 1.f / ssum;
        }
        __syncthreads();
        {   // weighted V: thread = (i = ib*32+il, toks oct*4..+3 and 32+oct*4..+3)
            const float* evec = e32 + il*E32P;
            ull a0 = 0, a1 = 0, a2 = 0, a3 = 0;
            for (int j4 = 0; j4 < 256; j4 += 4){
                float4 e4 = *(const float4*)(evec + j4);
                #pragma unroll
                for (int u = 0; u < 4; u++){
                    float e = (u == 0) ? e4.x : (u == 1) ? e4.y : (u == 2) ? e4.z : e4.w;
                    ull ed = pack2(e, e);
                    const float* vr = vsm + (j4 + u)*64 + oct*4;
                    ulonglong2 v0 = *(const ulonglong2*)(vr);        // toks oct*4..+3
                    ulonglong2 v1 = *(const ulonglong2*)(vr + 32);   // toks 32+oct*4..+3
                    a0 = fma2(ed, v0.x, a0);
                    a1 = fma2(ed, v0.y, a1);
                    a2 = fma2(ed, v1.x, a2);
                    a3 = fma2(ed, v1.y, a3);
                }
            }
            float rd = rden[il];
            float* dst = vg + (size_t)(ib*32 + il)*64;   // overwrite g_v in place with Y
            float2 u0 = unpack2(a0), u1 = unpack2(a1), u2 = unpack2(a2), u3 = unpack2(a3);
            float4 w0 = {u0.x*rd, u0.y*rd, u1.x*rd, u1.y*rd};
            float4 w1 = {u2.x*rd, u2.y*rd, u3.x*rd, u3.y*rd};
            *(float4*)(dst + oct*4)      = w0;
            *(float4*)(dst + 32 + oct*4) = w1;
        }
    }
}

// ---------------- kernel C: projection GEMM per window ----------------
// smem: ys[64][193], ws[KT][192], qs[64][193]
#define SMEM_C ((64*193 + KT*192 + 64*193) * 4)

__global__ void __launch_bounds__(256, 2) kProj(const float* __restrict__ proj_b,
                                                float* __restrict__ out){
    extern __shared__ float sm[];
    float* ys = sm;                  // [64 tok][193] (k = channel)
    float* ws = sm + 64*193;         // [KT][192]
    float* qs = ws + KT*192;         // [64][193]
    const int tid = threadIdx.x;
    const int blk = blockIdx.x;      // b*256 + win
    const int b   = blk >> 8;
    const int win = blk & 255;

    // gather y: g_v[b][c][win][tok] -> ys[tok][193] (scalar STS; 193-pitch rows)
    #pragma unroll
    for (int it = 0; it < 12; it++){
        int idx = it*256 + tid;           // 0..3071 = 192 ch * 16 tok-quads
        int c = idx / 16, t4 = idx % 16;
        float4 v = *(const float4*)(g_v + ((size_t)(b*192 + c)*256 + win)*64 + t4*4);
        ys[(t4*4+0)*193 + c] = v.x;
        ys[(t4*4+1)*193 + c] = v.y;
        ys[(t4*4+2)*193 + c] = v.z;
        ys[(t4*4+3)*193 + c] = v.w;
    }

    const int tx = tid & 15, ty = tid >> 4;
    const int obase = ty * 12;

    ull acc[4][6];
    {
        const float* bp = proj_b + obase;
        #pragma unroll
        for (int p = 0; p < 6; p++){
            ull bb = pack2(bp[2*p], bp[2*p+1]);
            acc[0][p]=bb; acc[1][p]=bb; acc[2][p]=bb; acc[3][p]=bb;
        }
    }
    for (int kt = 0; kt < 192/KT; kt++){
        __syncthreads();
        #pragma unroll
        for (int it = 0; it < 3; it++){
            int idx = it*256 + tid;
            int kk = idx / 48, o4 = idx % 48;
            *(float4*)(ws + kk*192 + o4*4) =
                *(const float4*)(g_pwT + (kt*KT+kk)*192 + o4*4);
        }
        __syncthreads();
        #pragma unroll
        for (int kk = 0; kk < KT; kk++)
            mma_step(ys, kt*KT+kk, tx, ws + kk*192 + obase, acc);
    }
    __syncthreads();
    #pragma unroll
    for (int t = 0; t < 4; t++){
        float* q = qs + (tx + t*16)*193 + obase;
        #pragma unroll
        for (int p = 0; p < 6; p++){
            float2 v = unpack2(acc[t][p]);
            q[2*p] = v.x; q[2*p+1] = v.y;
        }
    }
    __syncthreads();
    // coalesced store: out[blk][tok][192]
    float* ob = out + (size_t)blk * (64*192);
    #pragma unroll
    for (int it = 0; it < 12; it++){
        int idx = it*256 + tid;           // 0..3071
        int tok = idx / 48, o4 = idx % 48;
        float4 v;
        v.x = qs[tok*193 + o4*4 + 0];
        v.y = qs[tok*193 + o4*4 + 1];
        v.z = qs[tok*193 + o4*4 + 2];
        v.w = qs[tok*193 + o4*4 + 3];
        *(float4*)(ob + tok*192 + o4*4) = v;
    }
}

// ---------------- launch ----------------
extern "C" void kernel_launch(void* const* d_in, const int* in_sizes, int n_in,
                              void* d_out, int out_size){
    const float* x      = (const float*)d_in[0];
    const float* qkv_w  = (const float*)d_in[1];
    const float* qkv_b  = (const float*)d_in[2];
    const float* proj_w = (const float*)d_in[3];
    const float* proj_b = (const float*)d_in[4];
    float* out = (float*)d_out;

    cudaFuncSetAttribute(kQKV,  cudaFuncAttributeMaxDynamicSharedMemorySize, SMEM_A);
    cudaFuncSetAttribute(kAttn, cudaFuncAttributeMaxDynamicSharedMemorySize, SMEM_B);
    cudaFuncSetAttribute(kProj, cudaFuncAttributeMaxDynamicSharedMemorySize, SMEM_C);

    kTrans<<<432, 256>>>(qkv_w, proj_w);
    kQKV <<<2048, 256, SMEM_A>>>(x, qkv_b);
    kAttn<<<1536, 256, SMEM_B>>>();
    kProj<<<2048, 256, SMEM_C>>>(proj_b, out);
}

// round 9
// speedup vs baseline: 1.0003x; 1.0003x over previous
#include <cuda_runtime.h>
#include <cuda_bf16.h>
#include <cstdint>

// Problem constants: B=8, NWIN=256, N=64 tok, C=192, H=6, d=32
#define KT 16
typedef unsigned long long ull;

// ---------------- device scratch (no runtime allocation) ----------------
__device__ float g_wT [192*576];            // qkv_w transposed: [k][o]
__device__ float g_pwT[192*192];            // proj_w transposed: [k][o]
__device__ float g_v  [8*192*256*64];       // V: [b][c][win][tok]; overwritten in-place with attn out Y
__device__ float g_qg [8*192*256];          // [b][c][win]
__device__ float g_kg [8*192*256];

// ---------------- f32x2 helpers ----------------
__device__ __forceinline__ ull fma2(ull a, ull b, ull c){
    ull d; asm("fma.rn.f32x2 %0, %1, %2, %3;" : "=l"(d) : "l"(a), "l"(b), "l"(c)); return d;
}
__device__ __forceinline__ ull pack2(float lo, float hi){
    ull d; asm("mov.b64 %0, {%1, %2};" : "=l"(d) : "f"(lo), "f"(hi)); return d;
}
__device__ __forceinline__ float2 unpack2(ull v){
    float2 r; asm("mov.b64 {%0, %1}, %2;" : "=f"(r.x), "=f"(r.y) : "l"(v)); return r;
}

// Microtile step: 4 toks (tx, tx+16, tx+32, tx+48) x 12 outs, one k.
// xs layout [tok][193] (k-major access xs[tok*193+k]); ws row = 12 contiguous outs.
__device__ __forceinline__ void mma_step(const float* __restrict__ xs, int k, int tx,
                                         const float* __restrict__ wrow, ull acc[4][6]){
    ull xd[4];
    #pragma unroll
    for (int t = 0; t < 4; t++){
        float xv = xs[(tx + t*16)*193 + k];
        xd[t] = pack2(xv, xv);
    }
    ulonglong2 wA = *(const ulonglong2*)(wrow);
    ulonglong2 wB = *(const ulonglong2*)(wrow + 4);
    ulonglong2 wC = *(const ulonglong2*)(wrow + 8);
    ull wp[6] = {wA.x, wA.y, wB.x, wB.y, wC.x, wC.y};
    #pragma unroll
    for (int t = 0; t < 4; t++)
        #pragma unroll
        for (int p = 0; p < 6; p++)
            acc[t][p] = fma2(xd[t], wp[p], acc[t][p]);
}

// ---------------- kernel T: weight transpose to k-major ----------------
__global__ void kTrans(const float* __restrict__ qkv_w, const float* __restrict__ proj_w){
    int idx = blockIdx.x * 256 + threadIdx.x;
    if (idx < 576*192){ int o = idx / 192, k = idx % 192; g_wT [k*576 + o] = qkv_w [idx]; }
    if (idx < 192*192){ int o = idx / 192, k = idx % 192; g_pwT[k*192 + o] = proj_w[idx]; }
}

// ---------------- kernel A: QKV GEMM + grad magnitudes + V scatter ----------------
// smem: xs[64][193], ws[KT][192], qs[64][193]
#define SMEM_A ((64*193 + KT*192 + 64*193) * 4)

__global__ void __launch_bounds__(256, 2) kQKV(const float* __restrict__ x,
                                               const float* __restrict__ qkv_b){
    extern __shared__ float sm[];
    float* xs = sm;                  // [64][193]
    float* ws = sm + 64*193;         // [KT][192]
    float* qs = ws + KT*192;         // [64][193]
    const int tid = threadIdx.x;
    const int blk = blockIdx.x;      // b*256 + win
    const int b   = blk >> 8;
    const int win = blk & 255;
    const float* xw = x + (size_t)blk * (64*192);

    // load x window [tok][192] -> xs[tok][193]
    // float4 LDG (aligned: gmem row pitch 192) + 4 scalar STS (smem pitch 193 is
    // NOT 16B-aligned per row -> wide STS would trap; scalars are conflict-light)
    #pragma unroll
    for (int it = 0; it < 12; it++){
        int idx = it*256 + tid;           // 0..3071 = 64 tok * 48 quads
        int tok = idx / 48, c4 = idx % 48;
        float4 v = *(const float4*)(xw + tok*192 + c4*4);
        float* dst = xs + tok*193 + c4*4;
        dst[0] = v.x; dst[1] = v.y; dst[2] = v.z; dst[3] = v.w;
    }

    const int tx = tid & 15, ty = tid >> 4;
    const int obase = ty * 12;

    for (int s = 0; s < 3; s++){          // q, k, v chunks (192 outs each)
        ull acc[4][6];
        {
            const float* bp = qkv_b + s*192 + obase;
            #pragma unroll
            for (int p = 0; p < 6; p++){
                ull bb = pack2(bp[2*p], bp[2*p+1]);
                acc[0][p]=bb; acc[1][p]=bb; acc[2][p]=bb; acc[3][p]=bb;
            }
        }
        for (int kt = 0; kt < 192/KT; kt++){
            __syncthreads();              // xs ready / prev ws & qs consumers done
            #pragma unroll
            for (int it = 0; it < 3; it++){   // stage ws tile [KT][192]
                int idx = it*256 + tid;       // 0..767 quads
                int kk = idx / 48, o4 = idx % 48;
                *(float4*)(ws + kk*192 + o4*4) =
                    *(const float4*)(g_wT + (kt*KT+kk)*576 + s*192 + o4*4);
            }
            __syncthreads();
            #pragma unroll
            for (int kk = 0; kk < KT; kk++)
                mma_step(xs, kt*KT+kk, tx, ws + kk*192 + obase, acc);
        }
        __syncthreads();
        // write chunk to qs[tok][193] (scalar stores; rows not 16B-aligned)
        #pragma unroll
        for (int t = 0; t < 4; t++){
            float* q = qs + (tx + t*16)*193 + obase;
            #pragma unroll
            for (int p = 0; p < 6; p++){
                float2 v = unpack2(acc[t][p]);
                q[2*p] = v.x; q[2*p+1] = v.y;
            }
        }
        __syncthreads();
        if (s < 2){
            // grad magnitude per channel: 8x8 spatial, zero-padded forward diff
            if (tid < 192){
                float up[8];
                float sum = 0.f;
                #pragma unroll
                for (int yy = 0; yy < 8; yy++){
                    float left = 0.f;
                    #pragma unroll
                    for (int xx = 0; xx < 8; xx++){
                        float cur = qs[(yy*8 + xx)*193 + tid];
                        sum += fabsf(cur - left) + fabsf(cur - (yy ? up[xx] : 0.f));
                        left = cur; up[xx] = cur;
                    }
                }
                if (s == 0) g_qg[(b*192 + tid)*256 + win] = sum * 0.17677669529663687f; // *d^-0.5
                else        g_kg[(b*192 + tid)*256 + win] = sum;
            }
        } else {
            // scatter v -> g_v[b][c][win][tok]
            #pragma unroll
            for (int it = 0; it < 12; it++){
                int idx = it*256 + tid;       // 0..3071 = 192 ch * 16 tok-quads
                int o = idx / 16, t4 = idx % 16;
                float4 v;
                v.x = qs[(t4*4+0)*193 + o];
                v.y = qs[(t4*4+1)*193 + o];
                v.z = qs[(t4*4+2)*193 + o];
                v.w = qs[(t4*4+3)*193 + o];
                *(float4*)(g_v + ((size_t)(b*192 + o)*256 + win)*64 + t4*4) = v;
            }
        }
    }
}

// ---------------- kernel B: softmax(rank-1 scores) @ V per (b, channel) ----------
// smem: vsm[256][64], e32[32][260], qgs[256], red[256], rden[32]
#define E32P 260
#define SMEM_B ((16384 + 32*E32P + 256 + 256 + 32) * 4)

__global__ void __launch_bounds__(256, 2) kAttn(){
    extern __shared__ float sm[];
    float* vsm  = sm;                 // [256 win][64 tok]
    float* e32  = sm + 16384;         // [32 i][260]
    float* qgs  = e32 + 32*E32P;      // [256]
    float* red  = qgs + 256;          // [256]
    float* rden = red + 256;          // [32]
    const int tid = threadIdx.x;
    const int bc  = blockIdx.x;       // b*192 + c
    const size_t base = (size_t)bc * 256;
    float* vg = g_v + base * 64;

    #pragma unroll
    for (int it = 0; it < 16; it++){
        int idx = it*256 + tid;
        *(float4*)(vsm + idx*4) = *(const float4*)(vg + idx*4);
    }
    qgs[tid] = g_qg[base + tid];
    float kg = g_kg[base + tid];
    red[tid] = kg;
    __syncthreads();
    #pragma unroll
    for (int off = 128; off >= 1; off >>= 1){
        if (tid < off) red[tid] = fmaxf(red[tid], red[tid + off]);
        __syncthreads();
    }
    const float kv = kg - red[0];     // kg_j - kg_max  (<= 0), j = tid

    const int il  = tid >> 3;         // i slot within 32-row block (0..31)
    const int oct = tid & 7;          // token octet (0..7)
    const int rot = (oct*4 + il) & 31;

    for (int ib = 0; ib < 8; ib++){
        const float* qrow = qgs + ib*32;
        __syncthreads();              // previous e32 consumers done
        #pragma unroll
        for (int r = 0; r < 32; r++)
            e32[r*E32P + tid] = __expf(qrow[r] * kv);
        __syncthreads();
        {   // denominators: 8 rotated 32-j segments per i
            const float* er = e32 + il*E32P + oct*32;
            float ssum = 0.f;
            #pragma unroll
            for (int jj = 0; jj < 32; jj++)
                ssum += er[(jj + rot) & 31];
            red[tid] = ssum;
        }
        __syncthreads();
        if (tid < 32){
            float ssum = 0.f;
            #pragma unroll
            for (int g2 = 0; g2 < 8; g2++) ssum += red[tid*8 + g2];
            rden[tid] = 1.f / ssum;
        }
        __syncthreads();
        {   // weighted V: thread = (i = ib*32+il, toks oct*4..+3 and 32+oct*4..+3)
            const float* evec = e32 + il*E32P;
            ull a0 = 0, a1 = 0, a2 = 0, a3 = 0;
            for (int j4 = 0; j4 < 256; j4 += 4){
                float4 e4 = *(const float4*)(evec + j4);
                #pragma unroll
                for (int u = 0; u < 4; u++){
                    float e = (u == 0) ? e4.x : (u == 1) ? e4.y : (u == 2) ? e4.z : e4.w;
                    ull ed = pack2(e, e);
                    const float* vr = vsm + (j4 + u)*64 + oct*4;
                    ulonglong2 v0 = *(const ulonglong2*)(vr);        // toks oct*4..+3
                    ulonglong2 v1 = *(const ulonglong2*)(vr + 32);   // toks 32+oct*4..+3
                    a0 = fma2(ed, v0.x, a0);
                    a1 = fma2(ed, v0.y, a1);
                    a2 = fma2(ed, v1.x, a2);
                    a3 = fma2(ed, v1.y, a3);
                }
            }
            float rd = rden[il];
            float* dst = vg + (size_t)(ib*32 + il)*64;   // overwrite g_v in place with Y
            float2 u0 = unpack2(a0), u1 = unpack2(a1), u2 = unpack2(a2), u3 = unpack2(a3);
            float4 w0 = {u0.x*rd, u0.y*rd, u1.x*rd, u1.y*rd};
            float4 w1 = {u2.x*rd, u2.y*rd, u3.x*rd, u3.y*rd};
            *(float4*)(dst + oct*4)      = w0;
            *(float4*)(dst + 32 + oct*4) = w1;
        }
    }
}

// ---------------- kernel C: projection GEMM per window ----------------
// smem: ys[64][193], ws[KT][192], qs[64][193]
#define SMEM_C ((64*193 + KT*192 + 64*193) * 4)

__global__ void __launch_bounds__(256, 2) kProj(const float* __restrict__ proj_b,
                                                float* __restrict__ out){
    extern __shared__ float sm[];
    float* ys = sm;                  // [64 tok][193] (k = channel)
    float* ws = sm + 64*193;         // [KT][192]
    float* qs = ws + KT*192;         // [64][193]
    const int tid = threadIdx.x;
    const int blk = blockIdx.x;      // b*256 + win
    const int b   = blk >> 8;
    const int win = blk & 255;

    // gather y: g_v[b][c][win][tok] -> ys[tok][193] (scalar STS; 193-pitch rows)
    #pragma unroll
    for (int it = 0; it < 12; it++){
        int idx = it*256 + tid;           // 0..3071 = 192 ch * 16 tok-quads
        int c = idx / 16, t4 = idx % 16;
        float4 v = *(const float4*)(g_v + ((size_t)(b*192 + c)*256 + win)*64 + t4*4);
        ys[(t4*4+0)*193 + c] = v.x;
        ys[(t4*4+1)*193 + c] = v.y;
        ys[(t4*4+2)*193 + c] = v.z;
        ys[(t4*4+3)*193 + c] = v.w;
    }

    const int tx = tid & 15, ty = tid >> 4;
    const int obase = ty * 12;

    ull acc[4][6];
    {
        const float* bp = proj_b + obase;
        #pragma unroll
        for (int p = 0; p < 6; p++){
            ull bb = pack2(bp[2*p], bp[2*p+1]);
            acc[0][p]=bb; acc[1][p]=bb; acc[2][p]=bb; acc[3][p]=bb;
        }
    }
    for (int kt = 0; kt < 192/KT; kt++){
        __syncthreads();
        #pragma unroll
        for (int it = 0; it < 3; it++){
            int idx = it*256 + tid;
            int kk = idx / 48, o4 = idx % 48;
            *(float4*)(ws + kk*192 + o4*4) =
                *(const float4*)(g_pwT + (kt*KT+kk)*192 + o4*4);
        }
        __syncthreads();
        #pragma unroll
        for (int kk = 0; kk < KT; kk++)
            mma_step(ys, kt*KT+kk, tx, ws + kk*192 + obase, acc);
    }
    __syncthreads();
    #pragma unroll
    for (int t = 0; t < 4; t++){
        float* q = qs + (tx + t*16)*193 + obase;
        #pragma unroll
        for (int p = 0; p < 6; p++){
            float2 v = unpack2(acc[t][p]);
            q[2*p] = v.x; q[2*p+1] = v.y;
        }
    }
    __syncthreads();
    // coalesced store: out[blk][tok][192]
    float* ob = out + (size_t)blk * (64*192);
    #pragma unroll
    for (int it = 0; it < 12; it++){
        int idx = it*256 + tid;           // 0..3071
        int tok = idx / 48, o4 = idx % 48;
        float4 v;
        v.x = qs[tok*193 + o4*4 + 0];
        v.y = qs[tok*193 + o4*4 + 1];
        v.z = qs[tok*193 + o4*4 + 2];
        v.w = qs[tok*193 + o4*4 + 3];
        *(float4*)(ob + tok*192 + o4*4) = v;
    }
}

// ---------------- launch ----------------
extern "C" void kernel_launch(void* const* d_in, const int* in_sizes, int n_in,
                              void* d_out, int out_size){
    const float* x      = (const float*)d_in[0];
    const float* qkv_w  = (const float*)d_in[1];
    const float* qkv_b  = (const float*)d_in[2];
    const float* proj_w = (const float*)d_in[3];
    const float* proj_b = (const float*)d_in[4];
    float* out = (float*)d_out;

    cudaFuncSetAttribute(kQKV,  cudaFuncAttributeMaxDynamicSharedMemorySize, SMEM_A);
    cudaFuncSetAttribute(kAttn, cudaFuncAttributeMaxDynamicSharedMemorySize, SMEM_B);
    cudaFuncSetAttribute(kProj, cudaFuncAttributeMaxDynamicSharedMemorySize, SMEM_C);

    kTrans<<<432, 256>>>(qkv_w, proj_w);
    kQKV <<<2048, 256, SMEM_A>>>(x, qkv_b);
    kAttn<<<1536, 256, SMEM_B>>>();
    kProj<<<2048, 256, SMEM_C>>>(proj_b, out);
}